// round 5
// baseline (speedup 1.0000x reference)
#include <cuda_runtime.h>
#include <cuda_fp16.h>
#include <math.h>
#include <float.h>
#include <stdint.h>

// ---------------- problem constants ----------------
#define TOKENS_TOTAL (32*2048)
#define IN_DIM   128
#define HID      64
#define OUT_DIM  64
#define CODEBOOK 2048

#define TB       128
#define NTHREADS 256
#define NBLOCKS  (TOKENS_TOTAL/TB)     // 512
#define XT_STRIDE 130
#define CCH      64                     // codes per chunk
#define NCH      (CODEBOOK/CCH)         // 32

// output layout: msg ++ idx(as float) ++ loss
#define MSG_ELEMS ((size_t)TOKENS_TOTAL*OUT_DIM)
#define IDX_OFF   MSG_ELEMS
#define LOSS_OFF  (MSG_ELEMS + TOKENS_TOTAL)

// ---------------- smem layout (float offsets) ----------------
#define OFF_E2   0                      // 2048 f
#define OFF_XT   2048                   // 64 x 130 f -> end 10368
#define OFF_W    10368                  // weights (<= 8192 f)
#define OFF_OBS  18560                  // obs tile / h2 (8192 f) -> end 26752
#define OFF_H1   2048                   // h1 overlays XT region (dead before XT write)
#define SMEM_FLOATS 26752               // 107008 B

// packed codebook: [h tile | l tile], each [2048 codes][32 words fp16x2],
// word order per code: q*8 + kb*2 + b  <->  original word kb*8 + 4b + q
#define CBW 32
__device__ uint4 g_cbpack4[2 * CODEBOOK * CBW / 4];   // 512 KB, 16B-aligned
__device__ float g_e2[CODEBOOK];
__device__ float g_partial[NBLOCKS];

// ---------------- fp16 split helpers ----------------
__device__ __forceinline__ void split_h2(float x0, float x1, uint32_t& h, uint32_t& l) {
    __half h0 = __float2half_rn(x0);
    __half h1 = __float2half_rn(x1);
    float  l0 = x0 - __half2float(h0);
    float  l1 = x1 - __half2float(h1);
    __half2 hh = __halves2half2(h0, h1);
    __half2 ll = __floats2half2_rn(l0, l1);
    h = *(uint32_t*)&hh;
    l = *(uint32_t*)&ll;
}

__device__ __forceinline__ void mma16(float* c, const uint32_t* a, uint32_t b0, uint32_t b1) {
    asm volatile(
        "mma.sync.aligned.m16n8k16.row.col.f32.f16.f16.f32 "
        "{%0,%1,%2,%3}, {%4,%5,%6,%7}, {%8,%9}, {%0,%1,%2,%3};"
        : "+f"(c[0]), "+f"(c[1]), "+f"(c[2]), "+f"(c[3])
        : "r"(a[0]), "r"(a[1]), "r"(a[2]), "r"(a[3]), "r"(b0), "r"(b1));
}

// ---------------- packed fp32x2 helpers (MLP) ----------------
__device__ __forceinline__ unsigned long long dup2(float x) {
    unsigned long long r; asm("mov.b64 %0, {%1, %1};" : "=l"(r) : "f"(x)); return r;
}
__device__ __forceinline__ void ffma2(unsigned long long& d, unsigned long long a, unsigned long long b) {
    asm("fma.rn.f32x2 %0, %1, %2, %0;" : "+l"(d) : "l"(a), "l"(b));
}
__device__ __forceinline__ float lo32(unsigned long long v) { return __uint_as_float((unsigned)v); }
__device__ __forceinline__ float hi32(unsigned long long v) { return __uint_as_float((unsigned)(v >> 32)); }

// ---------------- MLP layer (proven rounds 1/3/4) ----------------
template<int KD, int NT, int OUTMODE, bool RELU>
__device__ __forceinline__ void mlp_layer(const float* in_s, int in_stride,
                                          const float* w_s, const float* __restrict__ b_g,
                                          float* out_s, int tid)
{
    const int jg = tid & 7;
    const int tg = tid >> 3;
    float bj[4][2];
#pragma unroll
    for (int jj = 0; jj < 4; jj++) {
        int j0 = jg*2 + 16*jj;
        bj[jj][0] = __ldg(b_g + j0);
        bj[jj][1] = __ldg(b_g + j0 + 1);
    }
    unsigned long long acc[NT][4];
#pragma unroll
    for (int it = 0; it < NT; it++)
#pragma unroll
        for (int jj = 0; jj < 4; jj++) acc[it][jj] = 0ULL;

#pragma unroll 4
    for (int k0 = 0; k0 < KD; k0 += 4) {
        float xin[NT][4];
#pragma unroll
        for (int it = 0; it < NT; it++) {
            float4 v = *(const float4*)(in_s + (tg*NT + it)*in_stride + k0);
            xin[it][0] = v.x; xin[it][1] = v.y; xin[it][2] = v.z; xin[it][3] = v.w;
        }
#pragma unroll
        for (int kk = 0; kk < 4; kk++) {
            unsigned long long wp[4];
#pragma unroll
            for (int jj = 0; jj < 4; jj++)
                wp[jj] = *(const unsigned long long*)(w_s + (k0+kk)*64 + jg*2 + 16*jj);
#pragma unroll
            for (int it = 0; it < NT; it++) {
                unsigned long long xd = dup2(xin[it][kk]);
#pragma unroll
                for (int jj = 0; jj < 4; jj++) ffma2(acc[it][jj], xd, wp[jj]);
            }
        }
    }
#pragma unroll
    for (int it = 0; it < NT; it++) {
        int t = tg*NT + it;
#pragma unroll
        for (int jj = 0; jj < 4; jj++) {
            int j0 = jg*2 + 16*jj;
            float v0 = lo32(acc[it][jj]) + bj[jj][0];
            float v1 = hi32(acc[it][jj]) + bj[jj][1];
            if (RELU) { v0 = fmaxf(v0, 0.0f); v1 = fmaxf(v1, 0.0f); }
            if (OUTMODE == 0) {
                out_s[t*64 + j0]     = v0;
                out_s[t*64 + j0 + 1] = v1;
            } else {
                out_s[j0*XT_STRIDE + t]       = v0;
                out_s[(j0 + 1)*XT_STRIDE + t] = v1;
            }
        }
    }
}

// ---------------- prep: pack codebook (fp16 hi/lo, fragment order) + e2 ----------------
// 4 threads per code; thread q owns original words w = kb*8 + 4b + q (kb 0..3, b 0..1),
// which partition the 32 words across q = 0..3.
__global__ void prep_kernel(const float* __restrict__ cb) {
    int gt = blockIdx.x * 256 + threadIdx.x;
    int c  = gt >> 2;
    int q  = gt & 3;
    if (c >= CODEBOOK) return;

    uint32_t hw[8], lw[8];
    float sq = 0.0f;
#pragma unroll
    for (int s = 0; s < 8; s++) {
        int kb = s >> 1, b = s & 1;
        int w  = kb*8 + 4*b + q;
        float x0 = __ldg(cb + (size_t)c*OUT_DIM + 2*w);
        float x1 = __ldg(cb + (size_t)c*OUT_DIM + 2*w + 1);
        split_h2(x0, x1, hw[s], lw[s]);
        sq += x0*x0 + x1*x1;
    }
    uint32_t* pack = (uint32_t*)g_cbpack4;
    uint32_t* hrow = pack + c*CBW + q*8;
    uint32_t* lrow = hrow + CODEBOOK*CBW;
    *(uint4*)(hrow)     = make_uint4(hw[0], hw[1], hw[2], hw[3]);
    *(uint4*)(hrow + 4) = make_uint4(hw[4], hw[5], hw[6], hw[7]);
    *(uint4*)(lrow)     = make_uint4(lw[0], lw[1], lw[2], lw[3]);
    *(uint4*)(lrow + 4) = make_uint4(lw[4], lw[5], lw[6], lw[7]);

    sq += __shfl_xor_sync(0xffffffffu, sq, 1);
    sq += __shfl_xor_sync(0xffffffffu, sq, 2);
    if (q == 0) g_e2[c] = sq;
}

// ---------------- fused kernel ----------------
__global__ void __launch_bounds__(NTHREADS, 1)
vq_main(const float* __restrict__ obs,
        const float* __restrict__ W1, const float* __restrict__ b1,
        const float* __restrict__ W2, const float* __restrict__ b2,
        const float* __restrict__ W3, const float* __restrict__ b3,
        const float* __restrict__ cb,
        float* __restrict__ out)
{
    extern __shared__ float sm[];
    const int tid  = threadIdx.x;
    const int wid  = tid >> 5;
    const int lane = tid & 31;
    const int r    = lane >> 2;      // 0..7
    const int q    = lane & 3;       // 0..3
    const int tok0 = blockIdx.x * TB;

    // e2 table -> smem
    for (int i = tid; i < CODEBOOK; i += NTHREADS) sm[OFF_E2 + i] = g_e2[i];

    // ================= MLP (FFMA2, bit-identical to rounds 1/3/4) =================
    {
        const float4* w4 = (const float4*)W1;
        float4* d4 = (float4*)(sm + OFF_W);
        for (int i = tid; i < (IN_DIM*HID)/4; i += NTHREADS) d4[i] = w4[i];
    }
    for (int half = 0; half < 2; half++) {
        __syncthreads();
        const float4* o4 = (const float4*)(obs + (size_t)(tok0 + half*64) * IN_DIM);
        float4* d4 = (float4*)(sm + OFF_OBS);
        for (int i = tid; i < (64*IN_DIM)/4; i += NTHREADS) d4[i] = o4[i];
        __syncthreads();
        mlp_layer<IN_DIM, 2, 0, true>(sm + OFF_OBS, IN_DIM, sm + OFF_W, b1,
                                      sm + OFF_H1 + half*64*HID, tid);
    }
    __syncthreads();
    {
        const float4* w4 = (const float4*)W2;
        float4* d4 = (float4*)(sm + OFF_W);
        for (int i = tid; i < (HID*HID)/4; i += NTHREADS) d4[i] = w4[i];
    }
    __syncthreads();
    mlp_layer<HID, 4, 0, true>(sm + OFF_H1, HID, sm + OFF_W, b2, sm + OFF_OBS, tid);
    __syncthreads();
    {
        const float4* w4 = (const float4*)W3;
        float4* d4 = (float4*)(sm + OFF_W);
        for (int i = tid; i < (HID*OUT_DIM)/4; i += NTHREADS) d4[i] = w4[i];
    }
    __syncthreads();
    mlp_layer<HID, 4, 1, false>(sm + OFF_OBS, HID, sm + OFF_W, b3, sm + OFF_XT, tid);
    __syncthreads();

    // ========== A fragments (m16 x k64, fp16 hi/lo), built once per warp ==========
    const float* xsT = sm + OFF_XT;
    const int tokw = wid * 16;
    uint32_t Ah[4][4], Al[4][4];
#pragma unroll
    for (int kb = 0; kb < 4; kb++) {
        int k0 = kb*16;
        const float* x0 = xsT + tokw;
        float v00 = x0[(k0 + 2*q    )*XT_STRIDE + r];
        float v01 = x0[(k0 + 2*q + 1)*XT_STRIDE + r];
        float v10 = x0[(k0 + 2*q    )*XT_STRIDE + r + 8];
        float v11 = x0[(k0 + 2*q + 1)*XT_STRIDE + r + 8];
        float v20 = x0[(k0 + 2*q + 8)*XT_STRIDE + r];
        float v21 = x0[(k0 + 2*q + 9)*XT_STRIDE + r];
        float v30 = x0[(k0 + 2*q + 8)*XT_STRIDE + r + 8];
        float v31 = x0[(k0 + 2*q + 9)*XT_STRIDE + r + 8];
        split_h2(v00, v01, Ah[kb][0], Al[kb][0]);
        split_h2(v10, v11, Ah[kb][1], Al[kb][1]);
        split_h2(v20, v21, Ah[kb][2], Al[kb][2]);
        split_h2(v30, v31, Ah[kb][3], Al[kb][3]);
    }

    // ================= VQ: fp16 m16n8k16, 3-term split, B direct from packed global =================
    float best_d0 = FLT_MAX, best_d1 = FLT_MAX;
    int   best_c0 = 0,       best_c1 = 0;

    const uint32_t* __restrict__ cbh = (const uint32_t*)g_cbpack4;
    const uint32_t* __restrict__ cbl = cbh + CODEBOOK*CBW;

    for (int ch = 0; ch < NCH; ch++) {
#pragma unroll
        for (int grp = 0; grp < 2; grp++) {
            float accM[4][4], accC1[4][4], accC2[4][4];
#pragma unroll
            for (int g = 0; g < 4; g++)
#pragma unroll
                for (int j = 0; j < 4; j++) { accM[g][j]=0.f; accC1[g][j]=0.f; accC2[g][j]=0.f; }

            // per-g packed row base: code = ch*64 + grp*32 + g*8 + r
            int rb[4];
#pragma unroll
            for (int g = 0; g < 4; g++)
                rb[g] = (ch*CCH + grp*32 + g*8 + r)*CBW + q*8;

#pragma unroll
            for (int kb = 0; kb < 4; kb++) {
                uint2 bhv[4], blv[4];
#pragma unroll
                for (int g = 0; g < 4; g++) {
                    bhv[g] = *(const uint2*)(cbh + rb[g] + kb*2);
                    blv[g] = *(const uint2*)(cbl + rb[g] + kb*2);
                }
#pragma unroll
                for (int g = 0; g < 4; g++) mma16(accM[g],  Ah[kb], bhv[g].x, bhv[g].y);
#pragma unroll
                for (int g = 0; g < 4; g++) mma16(accC1[g], Ah[kb], blv[g].x, blv[g].y);
#pragma unroll
                for (int g = 0; g < 4; g++) mma16(accC2[g], Al[kb], bhv[g].x, bhv[g].y);
            }

            // epilogue: dist = e2 - 2*s, running argmin (codes ascending per slot)
#pragma unroll
            for (int g = 0; g < 4; g++) {
                int code0 = ch*CCH + grp*32 + g*8 + 2*q;
                float e20 = sm[OFF_E2 + code0];
                float e21 = sm[OFF_E2 + code0 + 1];
                float s0 = accM[g][0] + accC1[g][0] + accC2[g][0];
                float s1 = accM[g][1] + accC1[g][1] + accC2[g][1];
                float s2 = accM[g][2] + accC1[g][2] + accC2[g][2];
                float s3 = accM[g][3] + accC1[g][3] + accC2[g][3];
                float d0 = fmaf(-2.0f, s0, e20);
                float d1 = fmaf(-2.0f, s1, e21);
                float d2 = fmaf(-2.0f, s2, e20);
                float d3 = fmaf(-2.0f, s3, e21);
                if (d0 < best_d0) { best_d0 = d0; best_c0 = code0; }
                if (d1 < best_d0) { best_d0 = d1; best_c0 = code0 + 1; }
                if (d2 < best_d1) { best_d1 = d2; best_c1 = code0; }
                if (d3 < best_d1) { best_d1 = d3; best_c1 = code0 + 1; }
            }
        }
    }

    // ---- cross-lane argmin (4 lanes per token row), tie-break: smaller code ----
#pragma unroll
    for (int m = 1; m <= 2; m <<= 1) {
        float od0 = __shfl_xor_sync(0xffffffffu, best_d0, m);
        int   oc0 = __shfl_xor_sync(0xffffffffu, best_c0, m);
        float od1 = __shfl_xor_sync(0xffffffffu, best_d1, m);
        int   oc1 = __shfl_xor_sync(0xffffffffu, best_c1, m);
        if (od0 < best_d0 || (od0 == best_d0 && oc0 < best_c0)) { best_d0 = od0; best_c0 = oc0; }
        if (od1 < best_d1 || (od1 == best_d1 && oc1 < best_c1)) { best_d1 = od1; best_c1 = oc1; }
    }

    int* sIdx = (int*)(sm + OFF_W);      // W region dead now
    if (q == 0) {
        int t0 = tokw + r;
        sIdx[t0]     = best_c0;
        sIdx[t0 + 8] = best_c1;
        out[IDX_OFF + (size_t)(tok0 + t0)]     = (float)best_c0;
        out[IDX_OFF + (size_t)(tok0 + t0 + 8)] = (float)best_c1;
    }
    __syncthreads();

    // ---- msg write + commitment-loss partial (exact fp32 x) ----
    float part = 0.0f;
    for (int f = tid; f < TB*OUT_DIM; f += NTHREADS) {
        int t = f >> 6, j = f & 63;
        int c = sIdx[t];
        float qv = __ldg(cb + (size_t)c * OUT_DIM + j);
        float xv = xsT[j*XT_STRIDE + t];
        out[(size_t)(tok0 + t)*OUT_DIM + j] = xv + (qv - xv);
        float dd = qv - xv;
        part += dd * dd;
    }
#pragma unroll
    for (int o = 16; o > 0; o >>= 1)
        part += __shfl_down_sync(0xffffffffu, part, o);
    __shared__ float swred[8];
    if ((tid & 31) == 0) swred[tid >> 5] = part;
    __syncthreads();
    if (tid == 0) {
        float s = 0.0f;
#pragma unroll
        for (int w = 0; w < 8; w++) s += swred[w];
        g_partial[blockIdx.x] = s;
    }
}

// ---------------- deterministic loss reduction ----------------
__global__ void loss_reduce(float* __restrict__ out) {
    __shared__ float s[NBLOCKS];
    int t = threadIdx.x;
    s[t] = g_partial[t];
    __syncthreads();
    for (int o = NBLOCKS/2; o > 0; o >>= 1) {
        if (t < o) s[t] += s[t + o];
        __syncthreads();
    }
    if (t == 0) out[LOSS_OFF] = s[0] * (1.0f / (float)MSG_ELEMS);
}

extern "C" void kernel_launch(void* const* d_in, const int* in_sizes, int n_in,
                              void* d_out, int out_size)
{
    const float* obs = (const float*)d_in[0];
    const float* W1  = (const float*)d_in[1];
    const float* b1  = (const float*)d_in[2];
    const float* W2  = (const float*)d_in[3];
    const float* b2  = (const float*)d_in[4];
    const float* W3  = (const float*)d_in[5];
    const float* b3  = (const float*)d_in[6];
    const float* cb  = (const float*)d_in[7];
    float* out = (float*)d_out;

    cudaFuncSetAttribute(vq_main, cudaFuncAttributeMaxDynamicSharedMemorySize,
                         SMEM_FLOATS * (int)sizeof(float));

    prep_kernel<<<(CODEBOOK*4 + 255)/256, 256>>>(cb);
    vq_main<<<NBLOCKS, NTHREADS, SMEM_FLOATS * sizeof(float)>>>(
        obs, W1, b1, W2, b2, W3, b3, cb, out);
    loss_reduce<<<1, NBLOCKS>>>(out);
}

// round 6
// speedup vs baseline: 1.8002x; 1.8002x over previous
#include <cuda_runtime.h>
#include <cuda_fp16.h>
#include <math.h>
#include <float.h>
#include <stdint.h>

// ---------------- problem constants ----------------
#define TOKENS_TOTAL (32*2048)
#define IN_DIM   128
#define HID      64
#define OUT_DIM  64
#define CODEBOOK 2048

#define TB       128
#define NTHREADS 256
#define NBLOCKS  (TOKENS_TOTAL/TB)     // 512
#define XT_STRIDE 130
#define CCH      64                     // codes per staged chunk
#define NCH      (CODEBOOK/CCH)         // 32

// output layout: msg ++ idx(as float) ++ loss
#define MSG_ELEMS ((size_t)TOKENS_TOTAL*OUT_DIM)
#define IDX_OFF   MSG_ELEMS
#define LOSS_OFF  (MSG_ELEMS + TOKENS_TOTAL)

// ---------------- smem layout (word offsets; 1 word = 4B) ----------------
#define OFF_E2   0                      // 2048 f
#define OFF_XT   2048                   // 64 x 130 f -> end 10368
#define OFF_B    10368                  // 2 bufs x (h 64x36 + l 64x36) = 9216 w -> end 19584
#define B_ROW_W   36                    // words per code row (32 data + 4 pad) ; 144B, 16B-aligned
#define B_TILE_W  (64*B_ROW_W)          // 2304
#define B_BUF_W   (2*B_TILE_W)          // 4608 (h tile then l tile)
// MLP-phase overlays (regions dead during MLP)
#define OFF_W    10368                  // weights (<= 8192 f)
#define OFF_OBS  18560                  // obs tile / h2 (8192 f) -> end 26752
#define OFF_H1   2048                   // h1 overlays XT (XT written later)
#define SMEM_FLOATS 26752               // 107008 B ; x2 CTAs = 214016 <= 228KB

// packed codebook (natural word order): [hi | lo], each [2048 codes][32 fp16x2 words]
// word w = k-pair index (k = 2w, 2w+1)
#define CBW 32
__device__ uint4 g_cbpack4[2 * CODEBOOK * CBW / 4];   // 512 KB
__device__ float g_e2[CODEBOOK];
__device__ float g_partial[NBLOCKS];

// ---------------- fp16 split helpers ----------------
__device__ __forceinline__ void split_h2(float x0, float x1, uint32_t& h, uint32_t& l) {
    __half h0 = __float2half_rn(x0);
    __half h1 = __float2half_rn(x1);
    float  l0 = x0 - __half2float(h0);
    float  l1 = x1 - __half2float(h1);
    __half2 hh = __halves2half2(h0, h1);
    __half2 ll = __floats2half2_rn(l0, l1);
    h = *(uint32_t*)&hh;
    l = *(uint32_t*)&ll;
}

__device__ __forceinline__ void mma16(float* c, const uint32_t* a, uint32_t b0, uint32_t b1) {
    asm volatile(
        "mma.sync.aligned.m16n8k16.row.col.f32.f16.f16.f32 "
        "{%0,%1,%2,%3}, {%4,%5,%6,%7}, {%8,%9}, {%0,%1,%2,%3};"
        : "+f"(c[0]), "+f"(c[1]), "+f"(c[2]), "+f"(c[3])
        : "r"(a[0]), "r"(a[1]), "r"(a[2]), "r"(a[3]), "r"(b0), "r"(b1));
}

// ---------------- packed fp32x2 helpers (MLP) ----------------
__device__ __forceinline__ unsigned long long dup2(float x) {
    unsigned long long r; asm("mov.b64 %0, {%1, %1};" : "=l"(r) : "f"(x)); return r;
}
__device__ __forceinline__ void ffma2(unsigned long long& d, unsigned long long a, unsigned long long b) {
    asm("fma.rn.f32x2 %0, %1, %2, %0;" : "+l"(d) : "l"(a), "l"(b));
}
__device__ __forceinline__ float lo32(unsigned long long v) { return __uint_as_float((unsigned)v); }
__device__ __forceinline__ float hi32(unsigned long long v) { return __uint_as_float((unsigned)(v >> 32)); }

// ---------------- MLP layer (proven rounds 1/3/4) ----------------
template<int KD, int NT, int OUTMODE, bool RELU>
__device__ __forceinline__ void mlp_layer(const float* in_s, int in_stride,
                                          const float* w_s, const float* __restrict__ b_g,
                                          float* out_s, int tid)
{
    const int jg = tid & 7;
    const int tg = tid >> 3;
    float bj[4][2];
#pragma unroll
    for (int jj = 0; jj < 4; jj++) {
        int j0 = jg*2 + 16*jj;
        bj[jj][0] = __ldg(b_g + j0);
        bj[jj][1] = __ldg(b_g + j0 + 1);
    }
    unsigned long long acc[NT][4];
#pragma unroll
    for (int it = 0; it < NT; it++)
#pragma unroll
        for (int jj = 0; jj < 4; jj++) acc[it][jj] = 0ULL;

#pragma unroll 4
    for (int k0 = 0; k0 < KD; k0 += 4) {
        float xin[NT][4];
#pragma unroll
        for (int it = 0; it < NT; it++) {
            float4 v = *(const float4*)(in_s + (tg*NT + it)*in_stride + k0);
            xin[it][0] = v.x; xin[it][1] = v.y; xin[it][2] = v.z; xin[it][3] = v.w;
        }
#pragma unroll
        for (int kk = 0; kk < 4; kk++) {
            unsigned long long wp[4];
#pragma unroll
            for (int jj = 0; jj < 4; jj++)
                wp[jj] = *(const unsigned long long*)(w_s + (k0+kk)*64 + jg*2 + 16*jj);
#pragma unroll
            for (int it = 0; it < NT; it++) {
                unsigned long long xd = dup2(xin[it][kk]);
#pragma unroll
                for (int jj = 0; jj < 4; jj++) ffma2(acc[it][jj], xd, wp[jj]);
            }
        }
    }
#pragma unroll
    for (int it = 0; it < NT; it++) {
        int t = tg*NT + it;
#pragma unroll
        for (int jj = 0; jj < 4; jj++) {
            int j0 = jg*2 + 16*jj;
            float v0 = lo32(acc[it][jj]) + bj[jj][0];
            float v1 = hi32(acc[it][jj]) + bj[jj][1];
            if (RELU) { v0 = fmaxf(v0, 0.0f); v1 = fmaxf(v1, 0.0f); }
            if (OUTMODE == 0) {
                out_s[t*64 + j0]     = v0;
                out_s[t*64 + j0 + 1] = v1;
            } else {
                out_s[j0*XT_STRIDE + t]       = v0;
                out_s[(j0 + 1)*XT_STRIDE + t] = v1;
            }
        }
    }
}

// ---------------- prep: pack codebook (fp16 hi/lo, natural word order) + e2 ----------------
// 4 threads per code; thread q owns words w = q*8 .. q*8+7 (elements q*16 .. q*16+15)
__global__ void prep_kernel(const float* __restrict__ cb) {
    int gt = blockIdx.x * 256 + threadIdx.x;
    int c  = gt >> 2;
    int q  = gt & 3;
    if (c >= CODEBOOK) return;

    uint32_t hw[8], lw[8];
    float sq = 0.0f;
#pragma unroll
    for (int i = 0; i < 4; i++) {
        float4 f = *(const float4*)(cb + (size_t)c*OUT_DIM + q*16 + i*4);
        split_h2(f.x, f.y, hw[i*2],   lw[i*2]);
        split_h2(f.z, f.w, hw[i*2+1], lw[i*2+1]);
        sq += f.x*f.x + f.y*f.y + f.z*f.z + f.w*f.w;
    }
    uint32_t* pack = (uint32_t*)g_cbpack4;
    uint32_t* hrow = pack + c*CBW + q*8;
    uint32_t* lrow = hrow + CODEBOOK*CBW;
    *(uint4*)(hrow)     = make_uint4(hw[0], hw[1], hw[2], hw[3]);
    *(uint4*)(hrow + 4) = make_uint4(hw[4], hw[5], hw[6], hw[7]);
    *(uint4*)(lrow)     = make_uint4(lw[0], lw[1], lw[2], lw[3]);
    *(uint4*)(lrow + 4) = make_uint4(lw[4], lw[5], lw[6], lw[7]);

    sq += __shfl_xor_sync(0xffffffffu, sq, 1);
    sq += __shfl_xor_sync(0xffffffffu, sq, 2);
    if (q == 0) g_e2[c] = sq;
}

// ---------------- chunk staging: pure copy from packed global ----------------
__device__ __forceinline__ void b_copy_ld(int ch, int tid, uint4* v) {
    const uint4* hbase = g_cbpack4 + (size_t)ch*CCH*(CBW/4);
    const uint4* lbase = hbase + CODEBOOK*(CBW/4);
    v[0] = __ldg(hbase + tid);
    v[1] = __ldg(hbase + tid + 256);
    v[2] = __ldg(lbase + tid);
    v[3] = __ldg(lbase + tid + 256);
}
__device__ __forceinline__ void b_copy_st(uint32_t* bbuf, int tid, const uint4* v) {
    int c0 = tid >> 3;            // 0..31
    int w0 = (tid & 7) * 4;       // 0..28
    uint32_t* d0 = bbuf + c0*B_ROW_W + w0;
    *(uint4*)(d0)                        = v[0];
    *(uint4*)(d0 + 32*B_ROW_W)           = v[1];
    *(uint4*)(d0 + B_TILE_W)             = v[2];
    *(uint4*)(d0 + B_TILE_W + 32*B_ROW_W)= v[3];
}

// ---------------- fused kernel ----------------
__global__ void __launch_bounds__(NTHREADS, 2)
vq_main(const float* __restrict__ obs,
        const float* __restrict__ W1, const float* __restrict__ b1,
        const float* __restrict__ W2, const float* __restrict__ b2,
        const float* __restrict__ W3, const float* __restrict__ b3,
        const float* __restrict__ cb,
        float* __restrict__ out)
{
    extern __shared__ float sm[];
    const int tid  = threadIdx.x;
    const int wid  = tid >> 5;
    const int lane = tid & 31;
    const int r    = lane >> 2;      // 0..7
    const int q    = lane & 3;       // 0..3
    const int tok0 = blockIdx.x * TB;

    // e2 table -> smem
    for (int i = tid; i < CODEBOOK; i += NTHREADS) sm[OFF_E2 + i] = g_e2[i];

    // ================= MLP (FFMA2, bit-identical to rounds 1/3/4) =================
    {
        const float4* w4 = (const float4*)W1;
        float4* d4 = (float4*)(sm + OFF_W);
        for (int i = tid; i < (IN_DIM*HID)/4; i += NTHREADS) d4[i] = w4[i];
    }
    for (int half = 0; half < 2; half++) {
        __syncthreads();
        const float4* o4 = (const float4*)(obs + (size_t)(tok0 + half*64) * IN_DIM);
        float4* d4 = (float4*)(sm + OFF_OBS);
        for (int i = tid; i < (64*IN_DIM)/4; i += NTHREADS) d4[i] = o4[i];
        __syncthreads();
        mlp_layer<IN_DIM, 2, 0, true>(sm + OFF_OBS, IN_DIM, sm + OFF_W, b1,
                                      sm + OFF_H1 + half*64*HID, tid);
    }
    __syncthreads();
    {
        const float4* w4 = (const float4*)W2;
        float4* d4 = (float4*)(sm + OFF_W);
        for (int i = tid; i < (HID*HID)/4; i += NTHREADS) d4[i] = w4[i];
    }
    __syncthreads();
    mlp_layer<HID, 4, 0, true>(sm + OFF_H1, HID, sm + OFF_W, b2, sm + OFF_OBS, tid);
    __syncthreads();
    {
        const float4* w4 = (const float4*)W3;
        float4* d4 = (float4*)(sm + OFF_W);
        for (int i = tid; i < (HID*OUT_DIM)/4; i += NTHREADS) d4[i] = w4[i];
    }
    __syncthreads();
    mlp_layer<HID, 4, 1, false>(sm + OFF_OBS, HID, sm + OFF_W, b3, sm + OFF_XT, tid);
    __syncthreads();

    // ========== A fragments (m16 x k64, fp16 hi/lo), built once per warp ==========
    const float* xsT = sm + OFF_XT;
    const int tokw = wid * 16;
    uint32_t Ah[4][4], Al[4][4];
#pragma unroll
    for (int kb = 0; kb < 4; kb++) {
        int k0 = kb*16;
        const float* x0 = xsT + tokw;
        float v00 = x0[(k0 + 2*q    )*XT_STRIDE + r];
        float v01 = x0[(k0 + 2*q + 1)*XT_STRIDE + r];
        float v10 = x0[(k0 + 2*q    )*XT_STRIDE + r + 8];
        float v11 = x0[(k0 + 2*q + 1)*XT_STRIDE + r + 8];
        float v20 = x0[(k0 + 2*q + 8)*XT_STRIDE + r];
        float v21 = x0[(k0 + 2*q + 9)*XT_STRIDE + r];
        float v30 = x0[(k0 + 2*q + 8)*XT_STRIDE + r + 8];
        float v31 = x0[(k0 + 2*q + 9)*XT_STRIDE + r + 8];
        split_h2(v00, v01, Ah[kb][0], Al[kb][0]);
        split_h2(v10, v11, Ah[kb][1], Al[kb][1]);
        split_h2(v20, v21, Ah[kb][2], Al[kb][2]);
        split_h2(v30, v31, Ah[kb][3], Al[kb][3]);
    }

    // ================= VQ: fp16 m16n8k16, 3-term split, smem-staged B =================
    float best_d0 = FLT_MAX, best_d1 = FLT_MAX;
    int   best_c0 = 0,       best_c1 = 0;

    uint32_t* bw = (uint32_t*)(sm + OFF_B);

    // prologue: stage chunk 0 into buf 0
    {
        uint4 st[4];
        b_copy_ld(0, tid, st);
        b_copy_st(bw, tid, st);
        __syncthreads();
    }

    for (int ch = 0; ch < NCH; ch++) {
        const int buf = ch & 1;
        uint4 st[4];
        const bool more = (ch + 1 < NCH);
        if (more) b_copy_ld(ch + 1, tid, st);   // prefetch next chunk into regs

        const uint32_t* bh = bw + buf*B_BUF_W;
        const uint32_t* bl = bh + B_TILE_W;

#pragma unroll
        for (int grp = 0; grp < 2; grp++) {
            float accM[4][4], accC1[4][4], accC2[4][4];
#pragma unroll
            for (int g = 0; g < 4; g++)
#pragma unroll
                for (int j = 0; j < 4; j++) { accM[g][j]=0.f; accC1[g][j]=0.f; accC2[g][j]=0.f; }

            // B row base: code_local = grp*32 + g*8 + r ; word offset q + kb*8 (+4)
            int rb0 = (grp*32 +  0 + r)*B_ROW_W + q;
            int rb1 = (grp*32 +  8 + r)*B_ROW_W + q;
            int rb2 = (grp*32 + 16 + r)*B_ROW_W + q;
            int rb3 = (grp*32 + 24 + r)*B_ROW_W + q;

#pragma unroll
            for (int kb = 0; kb < 4; kb++) {
                int ko = kb*8;
                uint32_t bh0[4], bh1[4], bl0[4], bl1[4];
                bh0[0] = bh[rb0 + ko]; bh1[0] = bh[rb0 + ko + 4];
                bh0[1] = bh[rb1 + ko]; bh1[1] = bh[rb1 + ko + 4];
                bh0[2] = bh[rb2 + ko]; bh1[2] = bh[rb2 + ko + 4];
                bh0[3] = bh[rb3 + ko]; bh1[3] = bh[rb3 + ko + 4];
                bl0[0] = bl[rb0 + ko]; bl1[0] = bl[rb0 + ko + 4];
                bl0[1] = bl[rb1 + ko]; bl1[1] = bl[rb1 + ko + 4];
                bl0[2] = bl[rb2 + ko]; bl1[2] = bl[rb2 + ko + 4];
                bl0[3] = bl[rb3 + ko]; bl1[3] = bl[rb3 + ko + 4];
#pragma unroll
                for (int g = 0; g < 4; g++) mma16(accM[g],  Ah[kb], bh0[g], bh1[g]);
#pragma unroll
                for (int g = 0; g < 4; g++) mma16(accC1[g], Ah[kb], bl0[g], bl1[g]);
#pragma unroll
                for (int g = 0; g < 4; g++) mma16(accC2[g], Al[kb], bh0[g], bh1[g]);
            }

            // epilogue: dist = e2 - 2*s, running argmin (codes ascending per slot)
#pragma unroll
            for (int g = 0; g < 4; g++) {
                int code0 = ch*CCH + grp*32 + g*8 + 2*q;
                float e20 = sm[OFF_E2 + code0];
                float e21 = sm[OFF_E2 + code0 + 1];
                float s0 = accM[g][0] + accC1[g][0] + accC2[g][0];
                float s1 = accM[g][1] + accC1[g][1] + accC2[g][1];
                float s2 = accM[g][2] + accC1[g][2] + accC2[g][2];
                float s3 = accM[g][3] + accC1[g][3] + accC2[g][3];
                float d0 = fmaf(-2.0f, s0, e20);
                float d1 = fmaf(-2.0f, s1, e21);
                float d2 = fmaf(-2.0f, s2, e20);
                float d3 = fmaf(-2.0f, s3, e21);
                if (d0 < best_d0) { best_d0 = d0; best_c0 = code0; }
                if (d1 < best_d0) { best_d0 = d1; best_c0 = code0 + 1; }
                if (d2 < best_d1) { best_d1 = d2; best_c1 = code0; }
                if (d3 < best_d1) { best_d1 = d3; best_c1 = code0 + 1; }
            }
        }

        __syncthreads();                 // all warps done reading this buf
        if (more) b_copy_st(bw + (1 - buf)*B_BUF_W, tid, st);
        __syncthreads();                 // staged data visible
    }

    // ---- cross-lane argmin (4 lanes per token row), tie-break: smaller code ----
#pragma unroll
    for (int m = 1; m <= 2; m <<= 1) {
        float od0 = __shfl_xor_sync(0xffffffffu, best_d0, m);
        int   oc0 = __shfl_xor_sync(0xffffffffu, best_c0, m);
        float od1 = __shfl_xor_sync(0xffffffffu, best_d1, m);
        int   oc1 = __shfl_xor_sync(0xffffffffu, best_c1, m);
        if (od0 < best_d0 || (od0 == best_d0 && oc0 < best_c0)) { best_d0 = od0; best_c0 = oc0; }
        if (od1 < best_d1 || (od1 == best_d1 && oc1 < best_c1)) { best_d1 = od1; best_c1 = oc1; }
    }

    int* sIdx = (int*)(sm + OFF_B);      // B region dead now
    if (q == 0) {
        int t0 = tokw + r;
        sIdx[t0]     = best_c0;
        sIdx[t0 + 8] = best_c1;
        out[IDX_OFF + (size_t)(tok0 + t0)]     = (float)best_c0;
        out[IDX_OFF + (size_t)(tok0 + t0 + 8)] = (float)best_c1;
    }
    __syncthreads();

    // ---- msg write + commitment-loss partial (exact fp32 x) ----
    float part = 0.0f;
    for (int f = tid; f < TB*OUT_DIM; f += NTHREADS) {
        int t = f >> 6, j = f & 63;
        int c = sIdx[t];
        float qv = __ldg(cb + (size_t)c * OUT_DIM + j);
        float xv = xsT[j*XT_STRIDE + t];
        out[(size_t)(tok0 + t)*OUT_DIM + j] = xv + (qv - xv);
        float dd = qv - xv;
        part += dd * dd;
    }
#pragma unroll
    for (int o = 16; o > 0; o >>= 1)
        part += __shfl_down_sync(0xffffffffu, part, o);
    __shared__ float swred[8];
    if ((tid & 31) == 0) swred[tid >> 5] = part;
    __syncthreads();
    if (tid == 0) {
        float s = 0.0f;
#pragma unroll
        for (int w = 0; w < 8; w++) s += swred[w];
        g_partial[blockIdx.x] = s;
    }
}

// ---------------- deterministic loss reduction ----------------
__global__ void loss_reduce(float* __restrict__ out) {
    __shared__ float s[NBLOCKS];
    int t = threadIdx.x;
    s[t] = g_partial[t];
    __syncthreads();
    for (int o = NBLOCKS/2; o > 0; o >>= 1) {
        if (t < o) s[t] += s[t + o];
        __syncthreads();
    }
    if (t == 0) out[LOSS_OFF] = s[0] * (1.0f / (float)MSG_ELEMS);
}

extern "C" void kernel_launch(void* const* d_in, const int* in_sizes, int n_in,
                              void* d_out, int out_size)
{
    const float* obs = (const float*)d_in[0];
    const float* W1  = (const float*)d_in[1];
    const float* b1  = (const float*)d_in[2];
    const float* W2  = (const float*)d_in[3];
    const float* b2  = (const float*)d_in[4];
    const float* W3  = (const float*)d_in[5];
    const float* b3  = (const float*)d_in[6];
    const float* cb  = (const float*)d_in[7];
    float* out = (float*)d_out;

    cudaFuncSetAttribute(vq_main, cudaFuncAttributeMaxDynamicSharedMemorySize,
                         SMEM_FLOATS * (int)sizeof(float));

    prep_kernel<<<(CODEBOOK*4 + 255)/256, 256>>>(cb);
    vq_main<<<NBLOCKS, NTHREADS, SMEM_FLOATS * sizeof(float)>>>(
        obs, W1, b1, W2, b2, W3, b3, cb, out);
    loss_reduce<<<1, NBLOCKS>>>(out);
}